// round 16
// baseline (speedup 1.0000x reference)
#include <cuda_runtime.h>

#define NROWS   2048
#define NCOLS   9605
#define NTOT    (NROWS * NCOLS)
#define F4TOT   (NTOT / 4)                  // 4,917,760
#define NBLK_M  592                          // 4 blocks x 148 SMs, exact
#define NTHR_M  256
#define GS      (NBLK_M * NTHR_M)            // 151,552 float4 per sweep
#define NITER   8                            // 8*4*GS = 4,849,664
#define TAIL0   (NITER * 4 * GS)
#define NBLK_E  NROWS
#define NTHR_E  128
#define CAPS    96
#define CLIPV   0.05f
#define X_TH    2.58f                        // E[cand/row]~47; exact fallback

__device__ double             g_part[NBLK_M];
__device__ float              g_corr[NROWS];
__device__ int                g_cnt[NROWS];     // static zero; k_epi resets
__device__ unsigned long long g_cand[NROWS * CAPS];
__device__ unsigned           g_done;            // static zero; last epi blk resets

// --- math (lg2 units; ONE formula everywhere) -------------------------------
__device__ __forceinline__ float p_of(float xv) {
    return __fdividef(1.f, 1.f + __expf(-xv));
}
__device__ __forceinline__ float bw2_of(float xv, float yv) {
    float p   = p_of(xv);
    float t   = fmaxf(p - CLIPV, 0.f);       // 1-t == min(1.05-p,1) for p<=1
    float t4  = (t * t) * (t * t);
    bool  pos = yv > 0.5f;
    float arg = fmaxf(pos ? p : (1.f - t), 1e-8f);
    float w   = pos ? (1.f - p) : t4;
    return __log2f(arg) * w;
}
__device__ __forceinline__ unsigned long long mk_key(float p, int col) {
    return ((unsigned long long)__float_as_uint(p) << 32) |
           (unsigned long long)(0xFFFFFFFFu - (unsigned)col);
}
__device__ __forceinline__ void ins10(unsigned long long* tk,
                                      unsigned long long key) {
    if (key > tk[9]) {
        tk[9] = key;
        for (int i = 9; i > 0; i--)
            if (tk[i] > tk[i - 1]) {
                unsigned long long k0 = tk[i - 1];
                tk[i - 1] = tk[i]; tk[i] = k0;
            }
    }
}

// process 4 elements of one float4 pair; accumulates lg2 sum, harvests cands
__device__ __forceinline__ void proc4(float4 xv, float4 yv, int gi0, float& sum) {
    float xs[4] = {xv.x, xv.y, xv.z, xv.w};
    float ys[4] = {yv.x, yv.y, yv.z, yv.w};
#pragma unroll
    for (int k = 0; k < 4; k++) {
        float xvk = xs[k];
        float p   = p_of(xvk);
        float t   = fmaxf(p - CLIPV, 0.f);
        float t4  = (t * t) * (t * t);
        bool  pos = ys[k] > 0.5f;
        float arg = fmaxf(pos ? p : (1.f - t), 1e-8f);
        float w   = pos ? (1.f - p) : t4;
        sum += __log2f(arg) * w;
        if (xvk > X_TH) {                     // rare (~0.5%)
            int gi  = gi0 + k;
            int row = gi / NCOLS;             // const-div -> mulhi
            int col = gi - row * NCOLS;
            int slot = atomicAdd(&g_cnt[row], 1);
            if (slot < CAPS)
                g_cand[row * CAPS + slot] = mk_key(p, col);
        }
    }
}

// ---------------------------------------------------------------------------
// Pass 1: flat, perfectly balanced streaming sum + candidate harvest.
__global__ void __launch_bounds__(NTHR_M, 4)
k_main(const float* __restrict__ x, const float* __restrict__ y) {
    const int gid = blockIdx.x * NTHR_M + threadIdx.x;
    const float4* __restrict__ x4 = reinterpret_cast<const float4*>(x);
    const float4* __restrict__ y4 = reinterpret_cast<const float4*>(y);

    float sum = 0.f;                          // lg2 units
    for (int it = 0; it < NITER; it++) {
        int v = gid + it * (4 * GS);
        float4 xa = x4[v];
        float4 xb = x4[v + GS];
        float4 xc = x4[v + 2 * GS];
        float4 xd = x4[v + 3 * GS];
        float4 ya = y4[v];
        float4 yb = y4[v + GS];
        float4 yc = y4[v + 2 * GS];
        float4 yd = y4[v + 3 * GS];
        proc4(xa, ya, v * 4,            sum);
        proc4(xb, yb, (v + GS) * 4,     sum);
        proc4(xc, yc, (v + 2 * GS) * 4, sum);
        proc4(xd, yd, (v + 3 * GS) * 4, sum);
    }
    // tail: [TAIL0, F4TOT) — each thread handles at most one extra float4
    for (int v = TAIL0 + gid; v < F4TOT; v += GS) {
        float4 xa = x4[v];
        float4 ya = y4[v];
        proc4(xa, ya, v * 4, sum);
    }

    // block reduce -> per-block double partial
#pragma unroll
    for (int off = 16; off > 0; off >>= 1)
        sum += __shfl_down_sync(0xFFFFFFFFu, sum, off);
    __shared__ float s_warp[NTHR_M / 32];
    int lane = threadIdx.x & 31, wid = threadIdx.x >> 5;
    if (lane == 0) s_warp[wid] = sum;
    __syncthreads();
    if (threadIdx.x == 0) {
        float b = 0.f;
#pragma unroll
        for (int i = 0; i < NTHR_M / 32; i++) b += s_warp[i];
        g_part[blockIdx.x] = (double)b;
    }
}

// ---------------------------------------------------------------------------
// Pass 2: one block per row — flags, exact top-10, rank logic, correction.
// Last finishing block folds 592 main partials + 2048 corrections -> out.
__global__ void __launch_bounds__(NTHR_E)
k_epi(const float* __restrict__ x, const float* __restrict__ y,
      const int* __restrict__ ci, const int* __restrict__ ri,
      const int* __restrict__ di, const int* __restrict__ wl,
      float* __restrict__ out) {
    const int row = blockIdx.x, tid = threadIdx.x;
    __shared__ int s_flags;
    __shared__ int s_last;

    const float* __restrict__ xr = x + (size_t)row * NCOLS;
    const float* __restrict__ yr = y + (size_t)row * NCOLS;

    if (tid == 0) s_flags = 0;
    __syncthreads();

    for (int i = tid; i < 170; i += NTHR_E) {
        int idx = (i < 30) ? ci[i] : (i < 100) ? ri[i - 30] : di[i - 100];
        if (yr[idx] > 0.5f) {
            int bit = (i < 30) ? 1 : (i < 100) ? 2 : 4;
            atomicOr(&s_flags, bit);
        }
    }
    __syncthreads();

    if (tid == 0) {
        unsigned long long tk[10];
#pragma unroll
        for (int i = 0; i < 10; i++) tk[i] = 0ULL;

        int n = g_cnt[row];
        if (n < 10 || n > CAPS) {
            // exact fallback (astronomically rare): serial row rescan
            for (int c = 0; c < NCOLS; c++)
                ins10(tk, mk_key(p_of(xr[c]), c));
        } else {
            const unsigned long long* kr = g_cand + row * CAPS;
            for (int i = 0; i < n; i++) ins10(tk, kr[i]);
        }

        int fl = s_flags;
        bool has1 = fl & 1, has2 = fl & 2, has3 = fl & 4;
        bool only4 = !(has1 || has2 || has3);
        bool found = false;
        float fac[10];
        int   idx10[10];
#pragma unroll
        for (int q = 0; q < 10; q++) {
            int j = (int)(0xFFFFFFFFu - (unsigned)(tk[q] & 0xFFFFFFFFULL));
            int g = wl[j];
            bool in_map = g > 0;
            bool in_gt  = ((g == 1) && has1) || ((g == 2) && has2) ||
                          ((g == 3) && has3) || ((g == 4) && only4);
            float f = (in_map && only4) ? 0.5f : 1.f;      // ALPHA_OTHER
            if (in_map && !in_gt && !found) f *= 2.f;      // ALPHA1
            fac[q] = f;
            idx10[q] = j;
            found = found || (in_map && in_gt);
        }
        float extra = found ? 1.f : 2.f;                   // final ALPHA1 pass
        float corr = 0.f;
#pragma unroll
        for (int q = 0; q < 10; q++) {
            int j = idx10[q];
            corr += bw2_of(xr[j], yr[j]) * (fac[q] * extra - 1.f);
        }
        g_corr[row] = corr;                                // lg2 units
        g_cnt[row] = 0;                                    // reset for replay
        __threadfence();
        unsigned t = atomicAdd(&g_done, 1u);
        s_last = (t == NROWS - 1) ? 1 : 0;
    }
    __syncthreads();

    if (s_last) {
        __threadfence();
        double d = 0.0;
        for (int i = tid; i < NROWS; i += NTHR_E) d += (double)g_corr[i];
        for (int i = tid; i < NBLK_M; i += NTHR_E) d += g_part[i];
#pragma unroll
        for (int off = 16; off > 0; off >>= 1)
            d += __shfl_down_sync(0xFFFFFFFFu, d, off);
        __shared__ double s_dw[NTHR_E / 32];
        int lane = tid & 31, wid = tid >> 5;
        if (lane == 0) s_dw[wid] = d;
        __syncthreads();
        if (tid == 0) {
            double tsum = 0.0;
#pragma unroll
            for (int i = 0; i < NTHR_E / 32; i++) tsum += s_dw[i];
            out[0] = (float)(-tsum * 0.6931471805599453);  // lg2 -> ln
            g_done = 0;                                    // reset for replay
        }
    }
}

extern "C" void kernel_launch(void* const* d_in, const int* in_sizes, int n_in,
                              void* d_out, int out_size) {
    const float* x  = (const float*)d_in[0];
    const float* y  = (const float*)d_in[1];
    const int*   ci = (const int*)d_in[2];
    const int*   ri = (const int*)d_in[3];
    const int*   di = (const int*)d_in[4];
    const int*   wl = (const int*)d_in[5];

    k_main<<<NBLK_M, NTHR_M>>>(x, y);
    k_epi<<<NBLK_E, NTHR_E>>>(x, y, ci, ri, di, wl, (float*)d_out);
}